// round 12
// baseline (speedup 1.0000x reference)
#include <cuda_runtime.h>
#include <cuda_bf16.h>
#include <cstdint>

#define B_    512
#define C_    20000
#define DE    512
#define KD    2048          // K * Dp = 8 * 256
#define TEMP  0.07f
#define MOM   0.999f
#define NHN   16

// ---------------- scratch (device globals: allocation-free) ----------------
__device__ float g_sim[(size_t)B_ * C_];                 // 41 MB
__device__ float g_invp[C_];
__device__ float g_nce[B_];
__device__ float g_align[B_];
__device__ int   g_lab[B_];
__device__ int   g_invmap[C_];                           // class -> batch row (or -1)
__device__ __align__(16) __nv_bfloat16 g_qh[B_ * DE];
__device__ __align__(16) __nv_bfloat16 g_ql[B_ * DE];
__device__ __align__(16) __nv_bfloat16 g_ph[(size_t)C_ * DE];
__device__ __align__(16) __nv_bfloat16 g_pl[(size_t)C_ * DE];

// ---------------- helpers ----------------
__device__ __forceinline__ uint32_t pack_bf2(float lo, float hi) {
    __nv_bfloat16 a = __float2bfloat16_rn(lo);
    __nv_bfloat16 b = __float2bfloat16_rn(hi);
    return (uint32_t)__bfloat16_as_ushort(a) | ((uint32_t)__bfloat16_as_ushort(b) << 16);
}
__device__ __forceinline__ void cpasync16(uint32_t s, const void* g) {
    asm volatile("cp.async.cg.shared.global [%0], [%1], 16;" :: "r"(s), "l"(g));
}
#define CP_COMMIT() asm volatile("cp.async.commit_group;" ::: "memory")
#define CP_WAIT(n)  asm volatile("cp.async.wait_group %0;" :: "n"(n) : "memory")

// split one float4 into hi/lo bf16x2 pairs
__device__ __forceinline__ void split4(float4 x, uint2& uh, uint2& ul) {
    __nv_bfloat16 hx = __float2bfloat16_rn(x.x), hy = __float2bfloat16_rn(x.y);
    __nv_bfloat16 hz = __float2bfloat16_rn(x.z), hw = __float2bfloat16_rn(x.w);
    uh.x = (uint32_t)__bfloat16_as_ushort(hx) | ((uint32_t)__bfloat16_as_ushort(hy) << 16);
    uh.y = (uint32_t)__bfloat16_as_ushort(hz) | ((uint32_t)__bfloat16_as_ushort(hw) << 16);
    ul.x = pack_bf2(x.x - __bfloat162float(hx), x.y - __bfloat162float(hy));
    ul.y = pack_bf2(x.z - __bfloat162float(hz), x.w - __bfloat162float(hw));
}

// ---------------- 0a: clear inverse label map ----------------
__global__ void clear_invmap() {
    int i = blockIdx.x * blockDim.x + threadIdx.x;
    if (i < C_) g_invmap[i] = -1;
}

// ---------------- 0b: decode labels + scatter inverse map ----------------
__global__ void decode_labels(const int* __restrict__ raw) {
    __shared__ int is64;
    if (threadIdx.x == 0) {
        int odd_or = 0;
        for (int i = 1; i < 64; i += 2) odd_or |= raw[i];
        is64 = (odd_or == 0) ? 1 : 0;
    }
    __syncthreads();
    int t = threadIdx.x;           // 512 threads
    int v = is64 ? raw[2 * t] : raw[t];
    if (v < 0) v = 0;
    if (v >= C_) v = C_ - 1;
    g_lab[t] = v;
    g_invmap[v] = t;               // labels distinct -> no conflicts
}

// ---------------- 1: part-bank copy fused with EMA ----------------
// One pass: copy pbank -> out, applying EMA on labeled rows inline.
__global__ void copy_part_ema(const float4* __restrict__ src,
                              const float4* __restrict__ pf4,
                              float4* __restrict__ dst, int n4) {
    const float om = 1.0f - MOM;
    for (int i = blockIdx.x * blockDim.x + threadIdx.x; i < n4;
         i += gridDim.x * blockDim.x) {
        float4 v = src[i];
        int row = i >> 9;                 // KD/4 = 512 float4 per bank row
        int b = __ldg(&g_invmap[row]);
        if (b >= 0) {
            float4 s = pf4[(size_t)b * 512 + (i & 511)];
            v.x = MOM * v.x + om * s.x;
            v.y = MOM * v.y + om * s.y;
            v.z = MOM * v.z + om * s.z;
            v.w = MOM * v.w + om * s.w;
        }
        dst[i] = v;
    }
}

// ---------------- 3: fused proto prep + q prep ----------------
// warps [0, C_): embed copy + EMA + inv norm + bf16 split
// warps [C_, C_+B_): query scale + bf16 split
__global__ void proto_fused(const float* __restrict__ ebk, const float* __restrict__ emb,
                            float* __restrict__ oeb) {
    int w = (blockIdx.x * blockDim.x + threadIdx.x) >> 5;
    int lane = threadIdx.x & 31;
    if (w < C_) {
        const int inv = g_invmap[w];
        const float4* r = (const float4*)(ebk + (size_t)w * DE);
        float4 v[4];
#pragma unroll
        for (int i = 0; i < 4; i++) v[i] = r[lane + 32 * i];
        if (inv >= 0) {
            const float4* e = (const float4*)(emb + (size_t)inv * DE);
            const float om = 1.0f - MOM;
#pragma unroll
            for (int i = 0; i < 4; i++) {
                float4 ev = e[lane + 32 * i];
                v[i].x = MOM * v[i].x + om * ev.x;
                v[i].y = MOM * v[i].y + om * ev.y;
                v[i].z = MOM * v[i].z + om * ev.z;
                v[i].w = MOM * v[i].w + om * ev.w;
            }
        }
        float s = 0.0f;
#pragma unroll
        for (int i = 0; i < 4; i++)
            s += v[i].x * v[i].x + v[i].y * v[i].y + v[i].z * v[i].z + v[i].w * v[i].w;
#pragma unroll
        for (int o = 16; o; o >>= 1) s += __shfl_xor_sync(0xffffffffu, s, o);
        if (lane == 0) g_invp[w] = 1.0f / fmaxf(sqrtf(s), 1e-12f);

        float4* ob = (float4*)(oeb + (size_t)w * DE);
        uint2* ph = (uint2*)(g_ph + (size_t)w * DE);
        uint2* pl = (uint2*)(g_pl + (size_t)w * DE);
#pragma unroll
        for (int i = 0; i < 4; i++) {
            ob[lane + 32 * i] = v[i];
            uint2 uh, ul;
            split4(v[i], uh, ul);
            ph[lane + 32 * i] = uh;
            pl[lane + 32 * i] = ul;
        }
    } else if (w < C_ + B_) {
        const int b = w - C_;
        const float4* r = (const float4*)(emb + (size_t)b * DE);
        float4 v[4];
        float s = 0.0f;
#pragma unroll
        for (int i = 0; i < 4; i++) {
            v[i] = r[lane + 32 * i];
            s += v[i].x * v[i].x + v[i].y * v[i].y + v[i].z * v[i].z + v[i].w * v[i].w;
        }
#pragma unroll
        for (int o = 16; o; o >>= 1) s += __shfl_xor_sync(0xffffffffu, s, o);
        float inv = 1.0f / (fmaxf(sqrtf(s), 1e-12f) * TEMP);
        uint2* oh = (uint2*)(g_qh + (size_t)b * DE);
        uint2* ol = (uint2*)(g_ql + (size_t)b * DE);
#pragma unroll
        for (int i = 0; i < 4; i++) {
            float4 x = v[i];
            x.x *= inv; x.y *= inv; x.z *= inv; x.w *= inv;
            uint2 uh, ul;
            split4(x, uh, ul);
            oh[lane + 32 * i] = uh;
            ol[lane + 32 * i] = ul;
        }
    }
}

// ---------------- 5: tensor-core sim GEMM, 256x128 tile, 512 threads --------
// Per-warp inner loop identical to the proven R9 body (warp = 64x32 output).
// M tile doubled -> B operand traffic read 2x instead of 4x (LDGSTS-issue bound).
#define SA 40                       // smem row stride in bf16 (80 B)
#define NKT2 (DE / 32)              // 16 k-tiles
#define A_REG_B (256 * SA * 2)      // 20480 B per A array per stage
#define B_REG_B (128 * SA * 2)      // 10240 B per B array per stage
#define OFF_AL  (A_REG_B)
#define OFF_BH  (2 * A_REG_B)
#define OFF_BL  (2 * A_REG_B + B_REG_B)
#define STAGE_B (2 * A_REG_B + 2 * B_REG_B)   // 61440 B
#define GEMM_SMEM (2 * STAGE_B)               // 122880 B

#define LDSM4(r0, r1, r2, r3, addr) \
    asm volatile("ldmatrix.sync.aligned.m8n8.x4.shared.b16 {%0,%1,%2,%3}, [%4];" \
                 : "=r"(r0), "=r"(r1), "=r"(r2), "=r"(r3) : "r"(addr))

#define MMA16816(d, a, b0v, b1v) \
    asm volatile("mma.sync.aligned.m16n8k16.row.col.f32.bf16.bf16.f32 " \
                 "{%0,%1,%2,%3}, {%4,%5,%6,%7}, {%8,%9}, {%0,%1,%2,%3};" \
                 : "+f"(d.x), "+f"(d.y), "+f"(d.z), "+f"(d.w) \
                 : "r"(a[0]), "r"(a[1]), "r"(a[2]), "r"(a[3]), "r"(b0v), "r"(b1v))

__global__ __launch_bounds__(512, 1)
void sim_gemm_tc() {
    extern __shared__ __align__(16) char smem[];
    const uint32_t sbase = (uint32_t)__cvta_generic_to_shared(smem);

    const int tid  = threadIdx.x;
    const int lane = tid & 31;
    const int wid  = tid >> 5;          // 0..15
    const int wm   = wid >> 2;          // 0..3 along M
    const int wn   = wid & 3;           // 0..3 along N
    const int m_base = wm * 64;
    const int n_base = wn * 32;
    const int row0 = blockIdx.y * 256;  // batch (grid y = 2)
    const int col0 = blockIdx.x * 128;  // classes

    // fill mapping (512 threads, 3072 x 16B ops per stage: A 2048, B 1024)
    const int alr  = tid >> 1;                  // 0..255 A row
    const int aseg = (tid & 1) * 2;             // segs {0,1} or {2,3}
    const int blr  = tid >> 2;                  // 0..127 B row
    const int bseg = tid & 3;                   // one seg
    const char* gA_h = (const char*)(g_qh + (size_t)(row0 + alr) * DE);
    const char* gA_l = (const char*)(g_ql + (size_t)(row0 + alr) * DE);
    const char* gB_h = (const char*)(g_ph + (size_t)(col0 + blr) * DE);
    const char* gB_l = (const char*)(g_pl + (size_t)(col0 + blr) * DE);
    const uint32_t sArow = (uint32_t)(alr * 80);
    const uint32_t sBrow = (uint32_t)(blr * 80);

    auto load_stage = [&](int s, int kt) {
        const uint32_t st = sbase + s * STAGE_B;
        const size_t gk = (size_t)kt * 64;
#pragma unroll
        for (int j = 0; j < 2; j++) {
            const uint32_t so = sArow + (aseg + j) * 16;
            const size_t go = gk + (aseg + j) * 16;
            cpasync16(st + so,          gA_h + go);
            cpasync16(st + OFF_AL + so, gA_l + go);
        }
        {
            const uint32_t so = sBrow + bseg * 16;
            const size_t go = gk + bseg * 16;
            cpasync16(st + OFF_BH + so, gB_h + go);
            cpasync16(st + OFF_BL + so, gB_l + go);
        }
    };

    const int rA = (lane & 7) + ((lane >> 3) & 1) * 8;
    const int cA = ((lane >> 4) & 1) * 8;
    const int rB = (lane & 7) + ((lane >> 4) & 1) * 8;
    const int cB = ((lane >> 3) & 1) * 8;

    float4 acc[4][4];
#pragma unroll
    for (int i = 0; i < 4; i++)
#pragma unroll
        for (int j = 0; j < 4; j++) acc[i][j] = make_float4(0.f, 0.f, 0.f, 0.f);

    load_stage(0, 0);
    CP_COMMIT();

    for (int kt = 0; kt < NKT2; kt++) {
        const int s = kt & 1;
        if (kt + 1 < NKT2) {
            load_stage(s ^ 1, kt + 1);
            CP_COMMIT();
            CP_WAIT(1);
        } else {
            CP_WAIT(0);
        }
        __syncthreads();

        const uint32_t bAh = sbase + s * STAGE_B;
        const uint32_t bAl = bAh + OFF_AL;
        const uint32_t bBh = bAh + OFF_BH;
        const uint32_t bBl = bAh + OFF_BL;
#pragma unroll
        for (int kk = 0; kk < 2; kk++) {
            uint32_t Ah[4][4], Al[4][4], Bh[2][4], Bl[2][4];
#pragma unroll
            for (int im = 0; im < 4; im++) {
                uint32_t off = ((m_base + im * 16 + rA) * SA + kk * 16 + cA) * 2;
                LDSM4(Ah[im][0], Ah[im][1], Ah[im][2], Ah[im][3], bAh + off);
                LDSM4(Al[im][0], Al[im][1], Al[im][2], Al[im][3], bAl + off);
            }
#pragma unroll
            for (int t2 = 0; t2 < 2; t2++) {
                uint32_t off = ((n_base + t2 * 16 + rB) * SA + kk * 16 + cB) * 2;
                LDSM4(Bh[t2][0], Bh[t2][1], Bh[t2][2], Bh[t2][3], bBh + off);
                LDSM4(Bl[t2][0], Bl[t2][1], Bl[t2][2], Bl[t2][3], bBl + off);
            }
#pragma unroll
            for (int im = 0; im < 4; im++)
#pragma unroll
                for (int in = 0; in < 4; in++)
                    MMA16816(acc[im][in], Ah[im], Bh[in >> 1][(in & 1) * 2],
                             Bh[in >> 1][(in & 1) * 2 + 1]);
#pragma unroll
            for (int im = 0; im < 4; im++)
#pragma unroll
                for (int in = 0; in < 4; in++)
                    MMA16816(acc[im][in], Ah[im], Bl[in >> 1][(in & 1) * 2],
                             Bl[in >> 1][(in & 1) * 2 + 1]);
#pragma unroll
            for (int im = 0; im < 4; im++)
#pragma unroll
                for (int in = 0; in < 4; in++)
                    MMA16816(acc[im][in], Al[im], Bh[in >> 1][(in & 1) * 2],
                             Bh[in >> 1][(in & 1) * 2 + 1]);
        }
        __syncthreads();
    }

    // epilogue: scale by invp[col], write g_sim
    const int gq = lane >> 2;
    const int qp = (lane & 3) * 2;
#pragma unroll
    for (int im = 0; im < 4; im++) {
        const int r = row0 + m_base + im * 16 + gq;
        float* row_ptr0 = g_sim + (size_t)r * C_;
        float* row_ptr1 = g_sim + (size_t)(r + 8) * C_;
#pragma unroll
        for (int in = 0; in < 4; in++) {
            const int c = col0 + n_base + in * 8 + qp;
            if (c < C_) {
                const float ip0 = g_invp[c];
                const float ip1 = g_invp[c + 1];
                float4 a = acc[im][in];
                float2 lo = make_float2(a.x * ip0, a.y * ip1);
                float2 hi = make_float2(a.z * ip0, a.w * ip1);
                *(float2*)(row_ptr0 + c) = lo;
                *(float2*)(row_ptr1 + c) = hi;
            }
        }
    }
}

// ---------------- 6: top-16 negatives + logsumexp per row ----------------
__global__ __launch_bounds__(256)
void topk_lse() {
    __shared__ float cand[256 * NHN];
    const int b = blockIdx.x;
    const int tid = threadIdx.x;
    const int lab = g_lab[b];
    const float* row = g_sim + (size_t)b * C_;

    float lt[NHN];
#pragma unroll
    for (int i = 0; i < NHN; i++) lt[i] = -1e30f;

    const float4* row4 = (const float4*)row;
    for (int c4 = tid; c4 < C_ / 4; c4 += 256) {
        float4 v4 = row4[c4];
        const int cb = c4 * 4;
        float vv[4] = {v4.x, v4.y, v4.z, v4.w};
#pragma unroll
        for (int j = 0; j < 4; j++) {
            if (cb + j == lab) continue;
            float v = vv[j];
            if (v > lt[NHN - 1]) {
                int k = NHN - 1;
                while (k > 0 && lt[k - 1] < v) { lt[k] = lt[k - 1]; --k; }
                lt[k] = v;
            }
        }
    }
#pragma unroll
    for (int i = 0; i < NHN; i++) cand[tid * NHN + i] = lt[i];

    for (int s = 128; s >= 1; s >>= 1) {
        __syncthreads();
        if (tid < s) {
            const float* Aa = cand + tid * NHN;
            const float* Bb = cand + (tid + s) * NHN;
            float out[NHN];
            int i = 0, j = 0;
#pragma unroll
            for (int t = 0; t < NHN; t++) {
                float a = Aa[i], bv = Bb[j];
                if (a >= bv) { out[t] = a; i++; } else { out[t] = bv; j++; }
            }
#pragma unroll
            for (int t = 0; t < NHN; t++) cand[tid * NHN + t] = out[t];
        }
    }
    __syncthreads();
    if (tid == 0) {
        float pos = row[lab];
        float mx = pos;
#pragma unroll
        for (int i = 0; i < NHN; i++) mx = fmaxf(mx, cand[i]);
        float sum = __expf(pos - mx);
#pragma unroll
        for (int i = 0; i < NHN; i++) sum += __expf(cand[i] - mx);
        g_nce[b] = mx + logf(sum) - pos;
    }
}

// ---------------- 7: alignment loss per row ----------------
__global__ __launch_bounds__(256)
void align_row(const float* __restrict__ emb, const float* __restrict__ sat,
               const float* __restrict__ neb) {
    __shared__ float red[5][8];
    const int b = blockIdx.x;
    const int tid = threadIdx.x;
    const int lab = g_lab[b];
    const float* e = emb + (size_t)b * DE;
    const float* s = sat + (size_t)b * DE;
    const float* p = neb + (size_t)lab * DE;
    float ee = 0, ss = 0, pp = 0, ep = 0, sp = 0;
    for (int i = tid; i < DE; i += 256) {
        float ev = e[i], sv = s[i], pv = p[i];
        ee += ev * ev; ss += sv * sv; pp += pv * pv;
        ep += ev * pv; sp += sv * pv;
    }
#pragma unroll
    for (int o = 16; o; o >>= 1) {
        ee += __shfl_xor_sync(0xffffffffu, ee, o);
        ss += __shfl_xor_sync(0xffffffffu, ss, o);
        pp += __shfl_xor_sync(0xffffffffu, pp, o);
        ep += __shfl_xor_sync(0xffffffffu, ep, o);
        sp += __shfl_xor_sync(0xffffffffu, sp, o);
    }
    int w = tid >> 5;
    if ((tid & 31) == 0) {
        red[0][w] = ee; red[1][w] = ss; red[2][w] = pp; red[3][w] = ep; red[4][w] = sp;
    }
    __syncthreads();
    if (tid == 0) {
        float a0 = 0, a1 = 0, a2 = 0, a3 = 0, a4 = 0;
        for (int i = 0; i < 8; i++) {
            a0 += red[0][i]; a1 += red[1][i]; a2 += red[2][i];
            a3 += red[3][i]; a4 += red[4][i];
        }
        float dn = fmaxf(sqrtf(a0), 1e-12f);
        float sn = fmaxf(sqrtf(a1), 1e-12f);
        float pn = fmaxf(sqrtf(a2), 1e-12f);
        g_align[b] = 0.5f * ((1.0f - a3 / (dn * pn)) + (1.0f - a4 / (sn * pn)));
    }
}

// ---------------- 8: final scalar reduction ----------------
__global__ __launch_bounds__(512)
void finalize(float* __restrict__ out_loss) {
    __shared__ float s1[512], s2[512];
    int t = threadIdx.x;
    s1[t] = g_nce[t];
    s2[t] = g_align[t];
    __syncthreads();
    for (int s = 256; s >= 1; s >>= 1) {
        if (t < s) { s1[t] += s1[t + s]; s2[t] += s2[t + s]; }
        __syncthreads();
    }
    if (t == 0) {
        out_loss[0] = s1[0] / (float)B_;
        out_loss[1] = s2[0] / (float)B_;
    }
}

// ---------------- launch ----------------
extern "C" void kernel_launch(void* const* d_in, const int* in_sizes, int n_in,
                              void* d_out, int out_size) {
    const float* pf    = (const float*)d_in[0];     // [512, 8, 256]
    const float* emb   = (const float*)d_in[1];     // [512, 512]
    const float* sat   = (const float*)d_in[2];     // [512, 512]
    const float* pbank = (const float*)d_in[3];     // [20000, 8, 256]
    const float* ebank = (const float*)d_in[4];     // [20000, 512]
    const int*   labs  = (const int*)d_in[5];       // [512] int32/int64 auto-detected

    const int P = in_sizes[3];   // 40,960,000
    const int E = in_sizes[4];   // 10,240,000

    float* out    = (float*)d_out;
    float* out_pb = out;
    float* out_eb = out + P;
    float* out_ls = out + P + E;

    static bool attr_done = false;
    if (!attr_done) {
        cudaFuncSetAttribute(sim_gemm_tc,
                             cudaFuncAttributeMaxDynamicSharedMemorySize, GEMM_SMEM);
        attr_done = true;
    }

    // 0. labels + inverse map
    clear_invmap<<<(C_ + 255) / 256, 256>>>();
    decode_labels<<<1, B_>>>(labs);
    // 1. part-bank copy + EMA fused (one pass)
    copy_part_ema<<<2048, 256>>>((const float4*)pbank, (const float4*)pf,
                                 (float4*)out_pb, P / 4);
    // 2. fused embed copy + EMA + norms + splits + query prep
    proto_fused<<<(C_ + B_ + 7) / 8, 256>>>(ebank, emb, out_eb);
    // 3. GEMM (256x128 tile, 512 threads, R9-proven inner loop)
    dim3 ggrid((C_ + 127) / 128, B_ / 256);
    sim_gemm_tc<<<ggrid, 512, GEMM_SMEM>>>();
    // 4. top-k + logsumexp
    topk_lse<<<B_, 256>>>();
    // 5. alignment
    align_row<<<B_, 256>>>(emb, sat, out_eb);
    // 6. finalize scalars
    finalize<<<1, 512>>>(out_ls);
}

// round 13
// speedup vs baseline: 1.0898x; 1.0898x over previous
#include <cuda_runtime.h>
#include <cuda_bf16.h>
#include <cstdint>

#define B_    512
#define C_    20000
#define DE    512
#define KD    2048          // K * Dp = 8 * 256
#define TEMP  0.07f
#define MOM   0.999f
#define NHN   16

// ---------------- scratch (device globals: allocation-free) ----------------
__device__ float g_sim[(size_t)B_ * C_];                 // 41 MB
__device__ float g_invp[C_];
__device__ float g_nce[B_];
__device__ float g_align[B_];
__device__ int   g_lab[B_];
__device__ int   g_invmap[C_];                           // class -> batch row (or -1)
__device__ __align__(16) __nv_bfloat16 g_qh[B_ * DE];
__device__ __align__(16) __nv_bfloat16 g_ql[B_ * DE];
__device__ __align__(16) __nv_bfloat16 g_ph[(size_t)C_ * DE];
__device__ __align__(16) __nv_bfloat16 g_pl[(size_t)C_ * DE];

// ---------------- helpers ----------------
__device__ __forceinline__ uint32_t pack_bf2(float lo, float hi) {
    __nv_bfloat16 a = __float2bfloat16_rn(lo);
    __nv_bfloat16 b = __float2bfloat16_rn(hi);
    return (uint32_t)__bfloat16_as_ushort(a) | ((uint32_t)__bfloat16_as_ushort(b) << 16);
}
__device__ __forceinline__ void cpasync16(uint32_t s, const void* g) {
    asm volatile("cp.async.cg.shared.global [%0], [%1], 16;" :: "r"(s), "l"(g));
}
#define CP_COMMIT() asm volatile("cp.async.commit_group;" ::: "memory")
#define CP_WAIT(n)  asm volatile("cp.async.wait_group %0;" :: "n"(n) : "memory")

// split one float4 into hi/lo bf16x2 pairs
__device__ __forceinline__ void split4(float4 x, uint2& uh, uint2& ul) {
    __nv_bfloat16 hx = __float2bfloat16_rn(x.x), hy = __float2bfloat16_rn(x.y);
    __nv_bfloat16 hz = __float2bfloat16_rn(x.z), hw = __float2bfloat16_rn(x.w);
    uh.x = (uint32_t)__bfloat16_as_ushort(hx) | ((uint32_t)__bfloat16_as_ushort(hy) << 16);
    uh.y = (uint32_t)__bfloat16_as_ushort(hz) | ((uint32_t)__bfloat16_as_ushort(hw) << 16);
    ul.x = pack_bf2(x.x - __bfloat162float(hx), x.y - __bfloat162float(hy));
    ul.y = pack_bf2(x.z - __bfloat162float(hz), x.w - __bfloat162float(hw));
}

// ---------------- 0a: clear inverse label map ----------------
__global__ void clear_invmap() {
    int i = blockIdx.x * blockDim.x + threadIdx.x;
    if (i < C_) g_invmap[i] = -1;
}

// ---------------- 0b: decode labels + scatter inverse map ----------------
__global__ void decode_labels(const int* __restrict__ raw) {
    __shared__ int is64;
    if (threadIdx.x == 0) {
        int odd_or = 0;
        for (int i = 1; i < 64; i += 2) odd_or |= raw[i];
        is64 = (odd_or == 0) ? 1 : 0;
    }
    __syncthreads();
    int t = threadIdx.x;           // 512 threads
    int v = is64 ? raw[2 * t] : raw[t];
    if (v < 0) v = 0;
    if (v >= C_) v = C_ - 1;
    g_lab[t] = v;
    g_invmap[v] = t;               // labels distinct -> no conflicts
}

// ---------------- 1: part-bank copy fused with EMA (measured win in R12) ----
__global__ void copy_part_ema(const float4* __restrict__ src,
                              const float4* __restrict__ pf4,
                              float4* __restrict__ dst, int n4) {
    const float om = 1.0f - MOM;
    for (int i = blockIdx.x * blockDim.x + threadIdx.x; i < n4;
         i += gridDim.x * blockDim.x) {
        float4 v = src[i];
        int row = i >> 9;                 // KD/4 = 512 float4 per bank row
        int b = __ldg(&g_invmap[row]);
        if (b >= 0) {
            float4 s = pf4[(size_t)b * 512 + (i & 511)];
            v.x = MOM * v.x + om * s.x;
            v.y = MOM * v.y + om * s.y;
            v.z = MOM * v.z + om * s.z;
            v.w = MOM * v.w + om * s.w;
        }
        dst[i] = v;
    }
}

// ---------------- 3: fused proto prep + q prep ----------------
__global__ void proto_fused(const float* __restrict__ ebk, const float* __restrict__ emb,
                            float* __restrict__ oeb) {
    int w = (blockIdx.x * blockDim.x + threadIdx.x) >> 5;
    int lane = threadIdx.x & 31;
    if (w < C_) {
        const int inv = g_invmap[w];
        const float4* r = (const float4*)(ebk + (size_t)w * DE);
        float4 v[4];
#pragma unroll
        for (int i = 0; i < 4; i++) v[i] = r[lane + 32 * i];
        if (inv >= 0) {
            const float4* e = (const float4*)(emb + (size_t)inv * DE);
            const float om = 1.0f - MOM;
#pragma unroll
            for (int i = 0; i < 4; i++) {
                float4 ev = e[lane + 32 * i];
                v[i].x = MOM * v[i].x + om * ev.x;
                v[i].y = MOM * v[i].y + om * ev.y;
                v[i].z = MOM * v[i].z + om * ev.z;
                v[i].w = MOM * v[i].w + om * ev.w;
            }
        }
        float s = 0.0f;
#pragma unroll
        for (int i = 0; i < 4; i++)
            s += v[i].x * v[i].x + v[i].y * v[i].y + v[i].z * v[i].z + v[i].w * v[i].w;
#pragma unroll
        for (int o = 16; o; o >>= 1) s += __shfl_xor_sync(0xffffffffu, s, o);
        if (lane == 0) g_invp[w] = 1.0f / fmaxf(sqrtf(s), 1e-12f);

        float4* ob = (float4*)(oeb + (size_t)w * DE);
        uint2* ph = (uint2*)(g_ph + (size_t)w * DE);
        uint2* pl = (uint2*)(g_pl + (size_t)w * DE);
#pragma unroll
        for (int i = 0; i < 4; i++) {
            ob[lane + 32 * i] = v[i];
            uint2 uh, ul;
            split4(v[i], uh, ul);
            ph[lane + 32 * i] = uh;
            pl[lane + 32 * i] = ul;
        }
    } else if (w < C_ + B_) {
        const int b = w - C_;
        const float4* r = (const float4*)(emb + (size_t)b * DE);
        float4 v[4];
        float s = 0.0f;
#pragma unroll
        for (int i = 0; i < 4; i++) {
            v[i] = r[lane + 32 * i];
            s += v[i].x * v[i].x + v[i].y * v[i].y + v[i].z * v[i].z + v[i].w * v[i].w;
        }
#pragma unroll
        for (int o = 16; o; o >>= 1) s += __shfl_xor_sync(0xffffffffu, s, o);
        float inv = 1.0f / (fmaxf(sqrtf(s), 1e-12f) * TEMP);
        uint2* oh = (uint2*)(g_qh + (size_t)b * DE);
        uint2* ol = (uint2*)(g_ql + (size_t)b * DE);
#pragma unroll
        for (int i = 0; i < 4; i++) {
            float4 x = v[i];
            x.x *= inv; x.y *= inv; x.z *= inv; x.w *= inv;
            uint2 uh, ul;
            split4(x, uh, ul);
            oh[lane + 32 * i] = uh;
            ol[lane + 32 * i] = ul;
        }
    }
}

// ---------------- 5: tensor-core sim GEMM (R11/R9-proven body) --------------
#define SA 40                     // smem row stride in bf16 (80 B)
#define NKT2 (DE / 32)            // 16 k-tiles
#define ARR_B (128 * SA * 2)      // 10240 B per operand array per stage
#define STAGE_B (4 * ARR_B)       // 40960 B per stage
#define GEMM_SMEM (2 * STAGE_B)   // 81920 B

#define LDSM4(r0, r1, r2, r3, addr) \
    asm volatile("ldmatrix.sync.aligned.m8n8.x4.shared.b16 {%0,%1,%2,%3}, [%4];" \
                 : "=r"(r0), "=r"(r1), "=r"(r2), "=r"(r3) : "r"(addr))

#define MMA16816(d, a, b0v, b1v) \
    asm volatile("mma.sync.aligned.m16n8k16.row.col.f32.bf16.bf16.f32 " \
                 "{%0,%1,%2,%3}, {%4,%5,%6,%7}, {%8,%9}, {%0,%1,%2,%3};" \
                 : "+f"(d.x), "+f"(d.y), "+f"(d.z), "+f"(d.w) \
                 : "r"(a[0]), "r"(a[1]), "r"(a[2]), "r"(a[3]), "r"(b0v), "r"(b1v))

__global__ __launch_bounds__(256, 2)
void sim_gemm_tc() {
    extern __shared__ __align__(16) char smem[];
    const uint32_t sbase = (uint32_t)__cvta_generic_to_shared(smem);

    const int tid  = threadIdx.x;
    const int lane = tid & 31;
    const int wid  = tid >> 5;
    const int wm   = wid & 1;
    const int wn   = wid >> 1;
    const int m_base = wm * 64;
    const int n_base = wn * 32;
    const int row0 = blockIdx.y * 128;
    const int col0 = blockIdx.x * 128;

    const int lr   = tid >> 1;
    const int half = tid & 1;
    const char* gA_h = (const char*)(g_qh + (size_t)(row0 + lr) * DE + half * 16);
    const char* gA_l = (const char*)(g_ql + (size_t)(row0 + lr) * DE + half * 16);
    const char* gB_h = (const char*)(g_ph + (size_t)(col0 + lr) * DE + half * 16);
    const char* gB_l = (const char*)(g_pl + (size_t)(col0 + lr) * DE + half * 16);
    const uint32_t srow = (uint32_t)(lr * SA + half * 16) * 2;

    auto load_stage = [&](int s, int kt) {
        const uint32_t st = sbase + s * STAGE_B + srow;
        const size_t gk = (size_t)kt * 64;
        cpasync16(st + 0 * ARR_B,      gA_h + gk);
        cpasync16(st + 0 * ARR_B + 16, gA_h + gk + 16);
        cpasync16(st + 1 * ARR_B,      gA_l + gk);
        cpasync16(st + 1 * ARR_B + 16, gA_l + gk + 16);
        cpasync16(st + 2 * ARR_B,      gB_h + gk);
        cpasync16(st + 2 * ARR_B + 16, gB_h + gk + 16);
        cpasync16(st + 3 * ARR_B,      gB_l + gk);
        cpasync16(st + 3 * ARR_B + 16, gB_l + gk + 16);
    };

    const int rA = (lane & 7) + ((lane >> 3) & 1) * 8;
    const int cA = ((lane >> 4) & 1) * 8;
    const int rB = (lane & 7) + ((lane >> 4) & 1) * 8;
    const int cB = ((lane >> 3) & 1) * 8;

    float4 acc[4][4];
#pragma unroll
    for (int i = 0; i < 4; i++)
#pragma unroll
        for (int j = 0; j < 4; j++) acc[i][j] = make_float4(0.f, 0.f, 0.f, 0.f);

    load_stage(0, 0);
    CP_COMMIT();

    for (int kt = 0; kt < NKT2; kt++) {
        const int s = kt & 1;
        if (kt + 1 < NKT2) {
            load_stage(s ^ 1, kt + 1);
            CP_COMMIT();
            CP_WAIT(1);
        } else {
            CP_WAIT(0);
        }
        __syncthreads();

        const uint32_t bAh = sbase + s * STAGE_B;
        const uint32_t bAl = bAh + ARR_B;
        const uint32_t bBh = bAh + 2 * ARR_B;
        const uint32_t bBl = bAh + 3 * ARR_B;
#pragma unroll
        for (int kk = 0; kk < 2; kk++) {
            uint32_t Ah[4][4], Al[4][4], Bh[2][4], Bl[2][4];
#pragma unroll
            for (int im = 0; im < 4; im++) {
                uint32_t off = ((m_base + im * 16 + rA) * SA + kk * 16 + cA) * 2;
                LDSM4(Ah[im][0], Ah[im][1], Ah[im][2], Ah[im][3], bAh + off);
                LDSM4(Al[im][0], Al[im][1], Al[im][2], Al[im][3], bAl + off);
            }
#pragma unroll
            for (int t2 = 0; t2 < 2; t2++) {
                uint32_t off = ((n_base + t2 * 16 + rB) * SA + kk * 16 + cB) * 2;
                LDSM4(Bh[t2][0], Bh[t2][1], Bh[t2][2], Bh[t2][3], bBh + off);
                LDSM4(Bl[t2][0], Bl[t2][1], Bl[t2][2], Bl[t2][3], bBl + off);
            }
#pragma unroll
            for (int im = 0; im < 4; im++)
#pragma unroll
                for (int in = 0; in < 4; in++)
                    MMA16816(acc[im][in], Ah[im], Bh[in >> 1][(in & 1) * 2],
                             Bh[in >> 1][(in & 1) * 2 + 1]);
#pragma unroll
            for (int im = 0; im < 4; im++)
#pragma unroll
                for (int in = 0; in < 4; in++)
                    MMA16816(acc[im][in], Ah[im], Bl[in >> 1][(in & 1) * 2],
                             Bl[in >> 1][(in & 1) * 2 + 1]);
#pragma unroll
            for (int im = 0; im < 4; im++)
#pragma unroll
                for (int in = 0; in < 4; in++)
                    MMA16816(acc[im][in], Al[im], Bh[in >> 1][(in & 1) * 2],
                             Bh[in >> 1][(in & 1) * 2 + 1]);
        }
        __syncthreads();
    }

    // epilogue: scale by invp[col], write g_sim
    const int gq = lane >> 2;
    const int qp = (lane & 3) * 2;
#pragma unroll
    for (int im = 0; im < 4; im++) {
        const int r = row0 + m_base + im * 16 + gq;
        float* row_ptr0 = g_sim + (size_t)r * C_;
        float* row_ptr1 = g_sim + (size_t)(r + 8) * C_;
#pragma unroll
        for (int in = 0; in < 4; in++) {
            const int c = col0 + n_base + in * 8 + qp;
            if (c < C_) {
                const float ip0 = g_invp[c];
                const float ip1 = g_invp[c + 1];
                float4 a = acc[im][in];
                float2 lo = make_float2(a.x * ip0, a.y * ip1);
                float2 hi = make_float2(a.z * ip0, a.w * ip1);
                *(float2*)(row_ptr0 + c) = lo;
                *(float2*)(row_ptr1 + c) = hi;
            }
        }
    }
}

// ---------------- 6: top-16 negatives + logsumexp per row ----------------
__global__ __launch_bounds__(256)
void topk_lse() {
    __shared__ float cand[256 * NHN];
    const int b = blockIdx.x;
    const int tid = threadIdx.x;
    const int lab = g_lab[b];
    const float* row = g_sim + (size_t)b * C_;

    float lt[NHN];
#pragma unroll
    for (int i = 0; i < NHN; i++) lt[i] = -1e30f;

    const float4* row4 = (const float4*)row;
    for (int c4 = tid; c4 < C_ / 4; c4 += 256) {
        float4 v4 = row4[c4];
        const int cb = c4 * 4;
        float vv[4] = {v4.x, v4.y, v4.z, v4.w};
#pragma unroll
        for (int j = 0; j < 4; j++) {
            if (cb + j == lab) continue;
            float v = vv[j];
            if (v > lt[NHN - 1]) {
                int k = NHN - 1;
                while (k > 0 && lt[k - 1] < v) { lt[k] = lt[k - 1]; --k; }
                lt[k] = v;
            }
        }
    }
#pragma unroll
    for (int i = 0; i < NHN; i++) cand[tid * NHN + i] = lt[i];

    for (int s = 128; s >= 1; s >>= 1) {
        __syncthreads();
        if (tid < s) {
            const float* Aa = cand + tid * NHN;
            const float* Bb = cand + (tid + s) * NHN;
            float out[NHN];
            int i = 0, j = 0;
#pragma unroll
            for (int t = 0; t < NHN; t++) {
                float a = Aa[i], bv = Bb[j];
                if (a >= bv) { out[t] = a; i++; } else { out[t] = bv; j++; }
            }
#pragma unroll
            for (int t = 0; t < NHN; t++) cand[tid * NHN + t] = out[t];
        }
    }
    __syncthreads();
    if (tid == 0) {
        float pos = row[lab];
        float mx = pos;
#pragma unroll
        for (int i = 0; i < NHN; i++) mx = fmaxf(mx, cand[i]);
        float sum = __expf(pos - mx);
#pragma unroll
        for (int i = 0; i < NHN; i++) sum += __expf(cand[i] - mx);
        g_nce[b] = mx + logf(sum) - pos;
    }
}

// ---------------- 7: alignment loss per row ----------------
__global__ __launch_bounds__(256)
void align_row(const float* __restrict__ emb, const float* __restrict__ sat,
               const float* __restrict__ neb) {
    __shared__ float red[5][8];
    const int b = blockIdx.x;
    const int tid = threadIdx.x;
    const int lab = g_lab[b];
    const float* e = emb + (size_t)b * DE;
    const float* s = sat + (size_t)b * DE;
    const float* p = neb + (size_t)lab * DE;
    float ee = 0, ss = 0, pp = 0, ep = 0, sp = 0;
    for (int i = tid; i < DE; i += 256) {
        float ev = e[i], sv = s[i], pv = p[i];
        ee += ev * ev; ss += sv * sv; pp += pv * pv;
        ep += ev * pv; sp += sv * pv;
    }
#pragma unroll
    for (int o = 16; o; o >>= 1) {
        ee += __shfl_xor_sync(0xffffffffu, ee, o);
        ss += __shfl_xor_sync(0xffffffffu, ss, o);
        pp += __shfl_xor_sync(0xffffffffu, pp, o);
        ep += __shfl_xor_sync(0xffffffffu, ep, o);
        sp += __shfl_xor_sync(0xffffffffu, sp, o);
    }
    int w = tid >> 5;
    if ((tid & 31) == 0) {
        red[0][w] = ee; red[1][w] = ss; red[2][w] = pp; red[3][w] = ep; red[4][w] = sp;
    }
    __syncthreads();
    if (tid == 0) {
        float a0 = 0, a1 = 0, a2 = 0, a3 = 0, a4 = 0;
        for (int i = 0; i < 8; i++) {
            a0 += red[0][i]; a1 += red[1][i]; a2 += red[2][i];
            a3 += red[3][i]; a4 += red[4][i];
        }
        float dn = fmaxf(sqrtf(a0), 1e-12f);
        float sn = fmaxf(sqrtf(a1), 1e-12f);
        float pn = fmaxf(sqrtf(a2), 1e-12f);
        g_align[b] = 0.5f * ((1.0f - a3 / (dn * pn)) + (1.0f - a4 / (sn * pn)));
    }
}

// ---------------- 8: final scalar reduction ----------------
__global__ __launch_bounds__(512)
void finalize(float* __restrict__ out_loss) {
    __shared__ float s1[512], s2[512];
    int t = threadIdx.x;
    s1[t] = g_nce[t];
    s2[t] = g_align[t];
    __syncthreads();
    for (int s = 256; s >= 1; s >>= 1) {
        if (t < s) { s1[t] += s1[t + s]; s2[t] += s2[t + s]; }
        __syncthreads();
    }
    if (t == 0) {
        out_loss[0] = s1[0] / (float)B_;
        out_loss[1] = s2[0] / (float)B_;
    }
}

// ---------------- launch ----------------
extern "C" void kernel_launch(void* const* d_in, const int* in_sizes, int n_in,
                              void* d_out, int out_size) {
    const float* pf    = (const float*)d_in[0];     // [512, 8, 256]
    const float* emb   = (const float*)d_in[1];     // [512, 512]
    const float* sat   = (const float*)d_in[2];     // [512, 512]
    const float* pbank = (const float*)d_in[3];     // [20000, 8, 256]
    const float* ebank = (const float*)d_in[4];     // [20000, 512]
    const int*   labs  = (const int*)d_in[5];       // [512] int32/int64 auto-detected

    const int P = in_sizes[3];   // 40,960,000
    const int E = in_sizes[4];   // 10,240,000

    float* out    = (float*)d_out;
    float* out_pb = out;
    float* out_eb = out + P;
    float* out_ls = out + P + E;

    static bool attr_done = false;
    if (!attr_done) {
        cudaFuncSetAttribute(sim_gemm_tc,
                             cudaFuncAttributeMaxDynamicSharedMemorySize, GEMM_SMEM);
        attr_done = true;
    }

    // 0. labels + inverse map
    clear_invmap<<<(C_ + 255) / 256, 256>>>();
    decode_labels<<<1, B_>>>(labs);
    // 1. part-bank copy + EMA fused (one pass)
    copy_part_ema<<<2048, 256>>>((const float4*)pbank, (const float4*)pf,
                                 (float4*)out_pb, P / 4);
    // 2. fused embed copy + EMA + norms + splits + query prep
    proto_fused<<<(C_ + B_ + 7) / 8, 256>>>(ebank, emb, out_eb);
    // 3. GEMM (R11-proven 128x128 body, 2 CTA/SM)
    dim3 ggrid((C_ + 127) / 128, B_ / 128);
    sim_gemm_tc<<<ggrid, 256, GEMM_SMEM>>>();
    // 4. top-k + logsumexp
    topk_lse<<<B_, 256>>>();
    // 5. alignment
    align_row<<<B_, 256>>>(emb, sat, out_eb);
    // 6. finalize scalars
    finalize<<<1, 512>>>(out_ls);
}

// round 14
// speedup vs baseline: 1.2798x; 1.1743x over previous
#include <cuda_runtime.h>
#include <cuda_fp16.h>
#include <cuda_bf16.h>
#include <cstdint>

#define B_    512
#define C_    20000
#define DE    512
#define KD    2048          // K * Dp = 8 * 256
#define TEMP  0.07f
#define MOM   0.999f
#define NHN   16
#define BSCALE 64.0f        // proto pre-scale so fp16 lo-residuals stay normal
#define BINV   (1.0f / 64.0f)

// ---------------- scratch (device globals: allocation-free) ----------------
__device__ float g_sim[(size_t)B_ * C_];                 // 41 MB
__device__ float g_invp[C_];
__device__ float g_nce[B_];
__device__ float g_align[B_];
__device__ int   g_lab[B_];
__device__ int   g_invmap[C_];                           // class -> batch row (or -1)
__device__ __align__(16) __half g_qh[B_ * DE];           // fp16( q/(|q|*T) )
__device__ __align__(16) __half g_ph[(size_t)C_ * DE];   // fp16( 64*proto ) hi
__device__ __align__(16) __half g_pl[(size_t)C_ * DE];   // fp16 residual (lo)

// ---------------- helpers ----------------
__device__ __forceinline__ uint32_t pack_h2(float a, float b) {
    __half2 h = __floats2half2_rn(a, b);   // a -> low 16 bits
    return *reinterpret_cast<uint32_t*>(&h);
}
__device__ __forceinline__ void cpasync16(uint32_t s, const void* g) {
    asm volatile("cp.async.cg.shared.global [%0], [%1], 16;" :: "r"(s), "l"(g));
}
#define CP_COMMIT() asm volatile("cp.async.commit_group;" ::: "memory")
#define CP_WAIT(n)  asm volatile("cp.async.wait_group %0;" :: "n"(n) : "memory")

// split one float4 (pre-scaled) into fp16 hi + fp16 residual
__device__ __forceinline__ void split4h(float4 x, uint2& uh, uint2& ul) {
    __half hx = __float2half_rn(x.x), hy = __float2half_rn(x.y);
    __half hz = __float2half_rn(x.z), hw = __float2half_rn(x.w);
    uh.x = pack_h2(__half2float(hx), 0.f) | (pack_h2(__half2float(hy), 0.f) << 16);
    // simpler: direct bit pack
    uh.x = (uint32_t)__half_as_ushort(hx) | ((uint32_t)__half_as_ushort(hy) << 16);
    uh.y = (uint32_t)__half_as_ushort(hz) | ((uint32_t)__half_as_ushort(hw) << 16);
    ul.x = pack_h2(x.x - __half2float(hx), x.y - __half2float(hy));
    ul.y = pack_h2(x.z - __half2float(hz), x.w - __half2float(hw));
}

// ---------------- 0a: clear inverse label map ----------------
__global__ void clear_invmap() {
    int i = blockIdx.x * blockDim.x + threadIdx.x;
    if (i < C_) g_invmap[i] = -1;
}

// ---------------- 0b: decode labels + scatter inverse map ----------------
__global__ void decode_labels(const int* __restrict__ raw) {
    __shared__ int is64;
    if (threadIdx.x == 0) {
        int odd_or = 0;
        for (int i = 1; i < 64; i += 2) odd_or |= raw[i];
        is64 = (odd_or == 0) ? 1 : 0;
    }
    __syncthreads();
    int t = threadIdx.x;           // 512 threads
    int v = is64 ? raw[2 * t] : raw[t];
    if (v < 0) v = 0;
    if (v >= C_) v = C_ - 1;
    g_lab[t] = v;
    g_invmap[v] = t;               // labels distinct -> no conflicts
}

// ---------------- 1: part-bank copy fused with EMA ----------------
__global__ void copy_part_ema(const float4* __restrict__ src,
                              const float4* __restrict__ pf4,
                              float4* __restrict__ dst, int n4) {
    const float om = 1.0f - MOM;
    for (int i = blockIdx.x * blockDim.x + threadIdx.x; i < n4;
         i += gridDim.x * blockDim.x) {
        float4 v = src[i];
        int row = i >> 9;                 // KD/4 = 512 float4 per bank row
        int b = __ldg(&g_invmap[row]);
        if (b >= 0) {
            float4 s = pf4[(size_t)b * 512 + (i & 511)];
            v.x = MOM * v.x + om * s.x;
            v.y = MOM * v.y + om * s.y;
            v.z = MOM * v.z + om * s.z;
            v.w = MOM * v.w + om * s.w;
        }
        dst[i] = v;
    }
}

// ---------------- 3: fused proto prep + q prep (fp16 split) ----------------
__global__ void proto_fused(const float* __restrict__ ebk, const float* __restrict__ emb,
                            float* __restrict__ oeb) {
    int w = (blockIdx.x * blockDim.x + threadIdx.x) >> 5;
    int lane = threadIdx.x & 31;
    if (w < C_) {
        const int inv = g_invmap[w];
        const float4* r = (const float4*)(ebk + (size_t)w * DE);
        float4 v[4];
#pragma unroll
        for (int i = 0; i < 4; i++) v[i] = r[lane + 32 * i];
        if (inv >= 0) {
            const float4* e = (const float4*)(emb + (size_t)inv * DE);
            const float om = 1.0f - MOM;
#pragma unroll
            for (int i = 0; i < 4; i++) {
                float4 ev = e[lane + 32 * i];
                v[i].x = MOM * v[i].x + om * ev.x;
                v[i].y = MOM * v[i].y + om * ev.y;
                v[i].z = MOM * v[i].z + om * ev.z;
                v[i].w = MOM * v[i].w + om * ev.w;
            }
        }
        float s = 0.0f;
#pragma unroll
        for (int i = 0; i < 4; i++)
            s += v[i].x * v[i].x + v[i].y * v[i].y + v[i].z * v[i].z + v[i].w * v[i].w;
#pragma unroll
        for (int o = 16; o; o >>= 1) s += __shfl_xor_sync(0xffffffffu, s, o);
        if (lane == 0) g_invp[w] = 1.0f / fmaxf(sqrtf(s), 1e-12f);

        float4* ob = (float4*)(oeb + (size_t)w * DE);
        uint2* ph = (uint2*)(g_ph + (size_t)w * DE);
        uint2* pl = (uint2*)(g_pl + (size_t)w * DE);
#pragma unroll
        for (int i = 0; i < 4; i++) {
            ob[lane + 32 * i] = v[i];
            float4 x = v[i];   // pre-scale so residuals stay fp16-normal
            x.x *= BSCALE; x.y *= BSCALE; x.z *= BSCALE; x.w *= BSCALE;
            uint2 uh, ul;
            split4h(x, uh, ul);
            ph[lane + 32 * i] = uh;
            pl[lane + 32 * i] = ul;
        }
    } else if (w < C_ + B_) {
        const int b = w - C_;
        const float4* r = (const float4*)(emb + (size_t)b * DE);
        float4 v[4];
        float s = 0.0f;
#pragma unroll
        for (int i = 0; i < 4; i++) {
            v[i] = r[lane + 32 * i];
            s += v[i].x * v[i].x + v[i].y * v[i].y + v[i].z * v[i].z + v[i].w * v[i].w;
        }
#pragma unroll
        for (int o = 16; o; o >>= 1) s += __shfl_xor_sync(0xffffffffu, s, o);
        float inv = 1.0f / (fmaxf(sqrtf(s), 1e-12f) * TEMP);
        uint2* oh = (uint2*)(g_qh + (size_t)b * DE);
#pragma unroll
        for (int i = 0; i < 4; i++) {
            float4 x = v[i];
            x.x *= inv; x.y *= inv; x.z *= inv; x.w *= inv;
            __half hx = __float2half_rn(x.x), hy = __float2half_rn(x.y);
            __half hz = __float2half_rn(x.z), hw = __float2half_rn(x.w);
            uint2 uh;
            uh.x = (uint32_t)__half_as_ushort(hx) | ((uint32_t)__half_as_ushort(hy) << 16);
            uh.y = (uint32_t)__half_as_ushort(hz) | ((uint32_t)__half_as_ushort(hw) << 16);
            oh[lane + 32 * i] = uh;
        }
    }
}

// ---------------- 5: tensor-core sim GEMM (fp16 2-pass, 3 operand arrays) ---
#define SA 40                     // smem row stride in fp16 (80 B)
#define NKT2 (DE / 32)            // 16 k-tiles
#define ARR_B (128 * SA * 2)      // 10240 B per operand array per stage
#define STAGE_B (3 * ARR_B)       // 30720 B per stage (Ah, Bh, Bl)
#define GEMM_SMEM (2 * STAGE_B)   // 61440 B

#define LDSM4(r0, r1, r2, r3, addr) \
    asm volatile("ldmatrix.sync.aligned.m8n8.x4.shared.b16 {%0,%1,%2,%3}, [%4];" \
                 : "=r"(r0), "=r"(r1), "=r"(r2), "=r"(r3) : "r"(addr))

#define MMAF16(d, a, b0v, b1v) \
    asm volatile("mma.sync.aligned.m16n8k16.row.col.f32.f16.f16.f32 " \
                 "{%0,%1,%2,%3}, {%4,%5,%6,%7}, {%8,%9}, {%0,%1,%2,%3};" \
                 : "+f"(d.x), "+f"(d.y), "+f"(d.z), "+f"(d.w) \
                 : "r"(a[0]), "r"(a[1]), "r"(a[2]), "r"(a[3]), "r"(b0v), "r"(b1v))

__global__ __launch_bounds__(256, 2)
void sim_gemm_tc() {
    extern __shared__ __align__(16) char smem[];
    const uint32_t sbase = (uint32_t)__cvta_generic_to_shared(smem);

    const int tid  = threadIdx.x;
    const int lane = tid & 31;
    const int wid  = tid >> 5;
    const int wm   = wid & 1;
    const int wn   = wid >> 1;
    const int m_base = wm * 64;
    const int n_base = wn * 32;
    const int row0 = blockIdx.y * 128;
    const int col0 = blockIdx.x * 128;

    const int lr   = tid >> 1;
    const int half = tid & 1;
    const char* gA_h = (const char*)(g_qh + (size_t)(row0 + lr) * DE + half * 16);
    const char* gB_h = (const char*)(g_ph + (size_t)(col0 + lr) * DE + half * 16);
    const char* gB_l = (const char*)(g_pl + (size_t)(col0 + lr) * DE + half * 16);
    const uint32_t srow = (uint32_t)(lr * SA + half * 16) * 2;

    auto load_stage = [&](int s, int kt) {
        const uint32_t st = sbase + s * STAGE_B + srow;
        const size_t gk = (size_t)kt * 64;
        cpasync16(st + 0 * ARR_B,      gA_h + gk);
        cpasync16(st + 0 * ARR_B + 16, gA_h + gk + 16);
        cpasync16(st + 1 * ARR_B,      gB_h + gk);
        cpasync16(st + 1 * ARR_B + 16, gB_h + gk + 16);
        cpasync16(st + 2 * ARR_B,      gB_l + gk);
        cpasync16(st + 2 * ARR_B + 16, gB_l + gk + 16);
    };

    const int rA = (lane & 7) + ((lane >> 3) & 1) * 8;
    const int cA = ((lane >> 4) & 1) * 8;
    const int rB = (lane & 7) + ((lane >> 4) & 1) * 8;
    const int cB = ((lane >> 3) & 1) * 8;

    float4 acc[4][4];
#pragma unroll
    for (int i = 0; i < 4; i++)
#pragma unroll
        for (int j = 0; j < 4; j++) acc[i][j] = make_float4(0.f, 0.f, 0.f, 0.f);

    load_stage(0, 0);
    CP_COMMIT();

    for (int kt = 0; kt < NKT2; kt++) {
        const int s = kt & 1;
        if (kt + 1 < NKT2) {
            load_stage(s ^ 1, kt + 1);
            CP_COMMIT();
            CP_WAIT(1);
        } else {
            CP_WAIT(0);
        }
        __syncthreads();

        const uint32_t bAh = sbase + s * STAGE_B;
        const uint32_t bBh = bAh + ARR_B;
        const uint32_t bBl = bAh + 2 * ARR_B;
#pragma unroll
        for (int kk = 0; kk < 2; kk++) {
            uint32_t Ah[4][4], Bh[2][4], Bl[2][4];
#pragma unroll
            for (int im = 0; im < 4; im++) {
                uint32_t off = ((m_base + im * 16 + rA) * SA + kk * 16 + cA) * 2;
                LDSM4(Ah[im][0], Ah[im][1], Ah[im][2], Ah[im][3], bAh + off);
            }
#pragma unroll
            for (int t2 = 0; t2 < 2; t2++) {
                uint32_t off = ((n_base + t2 * 16 + rB) * SA + kk * 16 + cB) * 2;
                LDSM4(Bh[t2][0], Bh[t2][1], Bh[t2][2], Bh[t2][3], bBh + off);
                LDSM4(Bl[t2][0], Bl[t2][1], Bl[t2][2], Bl[t2][3], bBl + off);
            }
#pragma unroll
            for (int im = 0; im < 4; im++)
#pragma unroll
                for (int in = 0; in < 4; in++)
                    MMAF16(acc[im][in], Ah[im], Bh[in >> 1][(in & 1) * 2],
                           Bh[in >> 1][(in & 1) * 2 + 1]);
#pragma unroll
            for (int im = 0; im < 4; im++)
#pragma unroll
                for (int in = 0; in < 4; in++)
                    MMAF16(acc[im][in], Ah[im], Bl[in >> 1][(in & 1) * 2],
                           Bl[in >> 1][(in & 1) * 2 + 1]);
        }
        __syncthreads();
    }

    // epilogue: scale by invp[col]/64, write g_sim
    const int gq = lane >> 2;
    const int qp = (lane & 3) * 2;
#pragma unroll
    for (int im = 0; im < 4; im++) {
        const int r = row0 + m_base + im * 16 + gq;
        float* row_ptr0 = g_sim + (size_t)r * C_;
        float* row_ptr1 = g_sim + (size_t)(r + 8) * C_;
#pragma unroll
        for (int in = 0; in < 4; in++) {
            const int c = col0 + n_base + in * 8 + qp;
            if (c < C_) {
                const float ip0 = g_invp[c] * BINV;
                const float ip1 = g_invp[c + 1] * BINV;
                float4 a = acc[im][in];
                float2 lo = make_float2(a.x * ip0, a.y * ip1);
                float2 hi = make_float2(a.z * ip0, a.w * ip1);
                *(float2*)(row_ptr0 + c) = lo;
                *(float2*)(row_ptr1 + c) = hi;
            }
        }
    }
}

// ---------------- 6: top-16 negatives + logsumexp per row ----------------
__global__ __launch_bounds__(256)
void topk_lse() {
    __shared__ float cand[256 * NHN];
    const int b = blockIdx.x;
    const int tid = threadIdx.x;
    const int lab = g_lab[b];
    const float* row = g_sim + (size_t)b * C_;

    float lt[NHN];
#pragma unroll
    for (int i = 0; i < NHN; i++) lt[i] = -1e30f;

    const float4* row4 = (const float4*)row;
    for (int c4 = tid; c4 < C_ / 4; c4 += 256) {
        float4 v4 = row4[c4];
        const int cb = c4 * 4;
        float vv[4] = {v4.x, v4.y, v4.z, v4.w};
#pragma unroll
        for (int j = 0; j < 4; j++) {
            if (cb + j == lab) continue;
            float v = vv[j];
            if (v > lt[NHN - 1]) {
                int k = NHN - 1;
                while (k > 0 && lt[k - 1] < v) { lt[k] = lt[k - 1]; --k; }
                lt[k] = v;
            }
        }
    }
#pragma unroll
    for (int i = 0; i < NHN; i++) cand[tid * NHN + i] = lt[i];

    for (int s = 128; s >= 1; s >>= 1) {
        __syncthreads();
        if (tid < s) {
            const float* Aa = cand + tid * NHN;
            const float* Bb = cand + (tid + s) * NHN;
            float out[NHN];
            int i = 0, j = 0;
#pragma unroll
            for (int t = 0; t < NHN; t++) {
                float a = Aa[i], bv = Bb[j];
                if (a >= bv) { out[t] = a; i++; } else { out[t] = bv; j++; }
            }
#pragma unroll
            for (int t = 0; t < NHN; t++) cand[tid * NHN + t] = out[t];
        }
    }
    __syncthreads();
    if (tid == 0) {
        float pos = row[lab];
        float mx = pos;
#pragma unroll
        for (int i = 0; i < NHN; i++) mx = fmaxf(mx, cand[i]);
        float sum = __expf(pos - mx);
#pragma unroll
        for (int i = 0; i < NHN; i++) sum += __expf(cand[i] - mx);
        g_nce[b] = mx + logf(sum) - pos;
    }
}

// ---------------- 7: alignment loss per row ----------------
__global__ __launch_bounds__(256)
void align_row(const float* __restrict__ emb, const float* __restrict__ sat,
               const float* __restrict__ neb) {
    __shared__ float red[5][8];
    const int b = blockIdx.x;
    const int tid = threadIdx.x;
    const int lab = g_lab[b];
    const float* e = emb + (size_t)b * DE;
    const float* s = sat + (size_t)b * DE;
    const float* p = neb + (size_t)lab * DE;
    float ee = 0, ss = 0, pp = 0, ep = 0, sp = 0;
    for (int i = tid; i < DE; i += 256) {
        float ev = e[i], sv = s[i], pv = p[i];
        ee += ev * ev; ss += sv * sv; pp += pv * pv;
        ep += ev * pv; sp += sv * pv;
    }
#pragma unroll
    for (int o = 16; o; o >>= 1) {
        ee += __shfl_xor_sync(0xffffffffu, ee, o);
        ss += __shfl_xor_sync(0xffffffffu, ss, o);
        pp += __shfl_xor_sync(0xffffffffu, pp, o);
        ep += __shfl_xor_sync(0xffffffffu, ep, o);
        sp += __shfl_xor_sync(0xffffffffu, sp, o);
    }
    int w = tid >> 5;
    if ((tid & 31) == 0) {
        red[0][w] = ee; red[1][w] = ss; red[2][w] = pp; red[3][w] = ep; red[4][w] = sp;
    }
    __syncthreads();
    if (tid == 0) {
        float a0 = 0, a1 = 0, a2 = 0, a3 = 0, a4 = 0;
        for (int i = 0; i < 8; i++) {
            a0 += red[0][i]; a1 += red[1][i]; a2 += red[2][i];
            a3 += red[3][i]; a4 += red[4][i];
        }
        float dn = fmaxf(sqrtf(a0), 1e-12f);
        float sn = fmaxf(sqrtf(a1), 1e-12f);
        float pn = fmaxf(sqrtf(a2), 1e-12f);
        g_align[b] = 0.5f * ((1.0f - a3 / (dn * pn)) + (1.0f - a4 / (sn * pn)));
    }
}

// ---------------- 8: final scalar reduction ----------------
__global__ __launch_bounds__(512)
void finalize(float* __restrict__ out_loss) {
    __shared__ float s1[512], s2[512];
    int t = threadIdx.x;
    s1[t] = g_nce[t];
    s2[t] = g_align[t];
    __syncthreads();
    for (int s = 256; s >= 1; s >>= 1) {
        if (t < s) { s1[t] += s1[t + s]; s2[t] += s2[t + s]; }
        __syncthreads();
    }
    if (t == 0) {
        out_loss[0] = s1[0] / (float)B_;
        out_loss[1] = s2[0] / (float)B_;
    }
}

// ---------------- launch ----------------
extern "C" void kernel_launch(void* const* d_in, const int* in_sizes, int n_in,
                              void* d_out, int out_size) {
    const float* pf    = (const float*)d_in[0];     // [512, 8, 256]
    const float* emb   = (const float*)d_in[1];     // [512, 512]
    const float* sat   = (const float*)d_in[2];     // [512, 512]
    const float* pbank = (const float*)d_in[3];     // [20000, 8, 256]
    const float* ebank = (const float*)d_in[4];     // [20000, 512]
    const int*   labs  = (const int*)d_in[5];       // [512] int32/int64 auto-detected

    const int P = in_sizes[3];   // 40,960,000
    const int E = in_sizes[4];   // 10,240,000

    float* out    = (float*)d_out;
    float* out_pb = out;
    float* out_eb = out + P;
    float* out_ls = out + P + E;

    static bool attr_done = false;
    if (!attr_done) {
        cudaFuncSetAttribute(sim_gemm_tc,
                             cudaFuncAttributeMaxDynamicSharedMemorySize, GEMM_SMEM);
        attr_done = true;
    }

    // 0. labels + inverse map
    clear_invmap<<<(C_ + 255) / 256, 256>>>();
    decode_labels<<<1, B_>>>(labs);
    // 1. part-bank copy + EMA fused (one pass)
    copy_part_ema<<<2048, 256>>>((const float4*)pbank, (const float4*)pf,
                                 (float4*)out_pb, P / 4);
    // 2. fused embed copy + EMA + norms + fp16 splits + query prep
    proto_fused<<<(C_ + B_ + 7) / 8, 256>>>(ebank, emb, out_eb);
    // 3. GEMM (fp16 2-pass, 3 operand arrays, 2 CTA/SM)
    dim3 ggrid((C_ + 127) / 128, B_ / 128);
    sim_gemm_tc<<<ggrid, 256, GEMM_SMEM>>>();
    // 4. top-k + logsumexp
    topk_lse<<<B_, 256>>>();
    // 5. alignment
    align_row<<<B_, 256>>>(emb, sat, out_eb);
    // 6. finalize scalars
    finalize<<<1, 512>>>(out_ls);
}

// round 15
// speedup vs baseline: 1.4833x; 1.1590x over previous
#include <cuda_runtime.h>
#include <cuda_fp16.h>
#include <cstdint>

#define B_    512
#define C_    20000
#define DE    512
#define KD    2048          // K * Dp = 8 * 256
#define TEMP  0.07f
#define MOM   0.999f
#define NHN   16
#define BSCALE 64.0f        // proto pre-scale so fp16 lo-residuals stay normal
#define BINV   (1.0f / 64.0f)

#define NCHUNK  8           // K chunks of 64 fp16 cols
#define CHUNK_B 16384       // 128 rows x 128 B per (tile, chunk) block
#define NTILE_C 157         // class tiles of 128 (last padded with zeros)

// ---------------- scratch (device globals: allocation-free) ----------------
__device__ float g_sim[(size_t)B_ * C_];                 // 41 MB
__device__ float g_invp[C_];
__device__ float g_nce[B_];
__device__ float g_align[B_];
__device__ int   g_lab[B_];
__device__ int   g_invmap[C_];                           // class -> batch row (or -1)
// operand arrays in tiled + SW128-swizzled layout: [tile][chunk][16KB block]
__device__ __align__(128) __half g_qh[B_ * DE];                  // 4 tiles
__device__ __align__(128) __half g_ph[(size_t)NTILE_C * 128 * DE]; // 157 tiles (pad=0)
__device__ __align__(128) __half g_pl[(size_t)NTILE_C * 128 * DE];

__device__ __forceinline__ size_t tco(int tile, int ck) {   // block byte offset
    return ((size_t)tile * NCHUNK + ck) * CHUNK_B;
}
__device__ __forceinline__ uint32_t sw128(uint32_t b) { return b ^ ((b >> 3) & 0x70); }

// ---------------- helpers ----------------
__device__ __forceinline__ uint32_t pack_h2(float a, float b) {
    __half2 h = __floats2half2_rn(a, b);   // a -> low 16 bits
    return *reinterpret_cast<uint32_t*>(&h);
}

// ---------------- 0a: clear inverse label map ----------------
__global__ void clear_invmap() {
    int i = blockIdx.x * blockDim.x + threadIdx.x;
    if (i < C_) g_invmap[i] = -1;
}

// ---------------- 0b: decode labels + scatter inverse map ----------------
__global__ void decode_labels(const int* __restrict__ raw) {
    __shared__ int is64;
    if (threadIdx.x == 0) {
        int odd_or = 0;
        for (int i = 1; i < 64; i += 2) odd_or |= raw[i];
        is64 = (odd_or == 0) ? 1 : 0;
    }
    __syncthreads();
    int t = threadIdx.x;           // 512 threads
    int v = is64 ? raw[2 * t] : raw[t];
    if (v < 0) v = 0;
    if (v >= C_) v = C_ - 1;
    g_lab[t] = v;
    g_invmap[v] = t;               // labels distinct -> no conflicts
}

// ---------------- 1: part-bank copy fused with EMA ----------------
__global__ void copy_part_ema(const float4* __restrict__ src,
                              const float4* __restrict__ pf4,
                              float4* __restrict__ dst, int n4) {
    const float om = 1.0f - MOM;
    for (int i = blockIdx.x * blockDim.x + threadIdx.x; i < n4;
         i += gridDim.x * blockDim.x) {
        float4 v = src[i];
        int row = i >> 9;                 // KD/4 = 512 float4 per bank row
        int b = __ldg(&g_invmap[row]);
        if (b >= 0) {
            float4 s = pf4[(size_t)b * 512 + (i & 511)];
            v.x = MOM * v.x + om * s.x;
            v.y = MOM * v.y + om * s.y;
            v.z = MOM * v.z + om * s.z;
            v.w = MOM * v.w + om * s.w;
        }
        dst[i] = v;
    }
}

// ---------------- tiled+swizzled 8B store helper ----------------
__device__ __forceinline__ void store_tiled(__half* base, int tile, int rl, int c0,
                                            uint2 val) {
    // c0 = global k column (multiple of 4 fp16)
    const int ck = c0 >> 6;                    // 64 cols per chunk
    const int cc = c0 & 63;
    uint32_t b = (uint32_t)(rl * 128 + cc * 2);
    *(uint2*)((char*)base + tco(tile, ck) + sw128(b)) = val;
}

// ---------------- 3: fused proto prep + q prep (fp16 split, tiled out) ------
__global__ void proto_fused(const float* __restrict__ ebk, const float* __restrict__ emb,
                            float* __restrict__ oeb) {
    int w = (blockIdx.x * blockDim.x + threadIdx.x) >> 5;
    int lane = threadIdx.x & 31;
    if (w < C_) {
        const int inv = g_invmap[w];
        const float4* r = (const float4*)(ebk + (size_t)w * DE);
        float4 v[4];
#pragma unroll
        for (int i = 0; i < 4; i++) v[i] = r[lane + 32 * i];
        if (inv >= 0) {
            const float4* e = (const float4*)(emb + (size_t)inv * DE);
            const float om = 1.0f - MOM;
#pragma unroll
            for (int i = 0; i < 4; i++) {
                float4 ev = e[lane + 32 * i];
                v[i].x = MOM * v[i].x + om * ev.x;
                v[i].y = MOM * v[i].y + om * ev.y;
                v[i].z = MOM * v[i].z + om * ev.z;
                v[i].w = MOM * v[i].w + om * ev.w;
            }
        }
        float s = 0.0f;
#pragma unroll
        for (int i = 0; i < 4; i++)
            s += v[i].x * v[i].x + v[i].y * v[i].y + v[i].z * v[i].z + v[i].w * v[i].w;
#pragma unroll
        for (int o = 16; o; o >>= 1) s += __shfl_xor_sync(0xffffffffu, s, o);
        if (lane == 0) g_invp[w] = 1.0f / fmaxf(sqrtf(s), 1e-12f);

        float4* ob = (float4*)(oeb + (size_t)w * DE);
        const int tile = w >> 7, rl = w & 127;
#pragma unroll
        for (int i = 0; i < 4; i++) {
            ob[lane + 32 * i] = v[i];
            float4 x = v[i];
            x.x *= BSCALE; x.y *= BSCALE; x.z *= BSCALE; x.w *= BSCALE;
            __half hx = __float2half_rn(x.x), hy = __float2half_rn(x.y);
            __half hz = __float2half_rn(x.z), hw = __float2half_rn(x.w);
            uint2 uh, ul;
            uh.x = (uint32_t)__half_as_ushort(hx) | ((uint32_t)__half_as_ushort(hy) << 16);
            uh.y = (uint32_t)__half_as_ushort(hz) | ((uint32_t)__half_as_ushort(hw) << 16);
            ul.x = pack_h2(x.x - __half2float(hx), x.y - __half2float(hy));
            ul.y = pack_h2(x.z - __half2float(hz), x.w - __half2float(hw));
            const int c0 = 4 * (lane + 32 * i);
            store_tiled(g_ph, tile, rl, c0, uh);
            store_tiled(g_pl, tile, rl, c0, ul);
        }
    } else if (w < C_ + B_) {
        const int b = w - C_;
        const float4* r = (const float4*)(emb + (size_t)b * DE);
        float4 v[4];
        float s = 0.0f;
#pragma unroll
        for (int i = 0; i < 4; i++) {
            v[i] = r[lane + 32 * i];
            s += v[i].x * v[i].x + v[i].y * v[i].y + v[i].z * v[i].z + v[i].w * v[i].w;
        }
#pragma unroll
        for (int o = 16; o; o >>= 1) s += __shfl_xor_sync(0xffffffffu, s, o);
        float inv = 1.0f / (fmaxf(sqrtf(s), 1e-12f) * TEMP);
        const int tile = b >> 7, rl = b & 127;
#pragma unroll
        for (int i = 0; i < 4; i++) {
            float4 x = v[i];
            x.x *= inv; x.y *= inv; x.z *= inv; x.w *= inv;
            __half hx = __float2half_rn(x.x), hy = __float2half_rn(x.y);
            __half hz = __float2half_rn(x.z), hw = __float2half_rn(x.w);
            uint2 uh;
            uh.x = (uint32_t)__half_as_ushort(hx) | ((uint32_t)__half_as_ushort(hy) << 16);
            uh.y = (uint32_t)__half_as_ushort(hz) | ((uint32_t)__half_as_ushort(hw) << 16);
            store_tiled(g_qh, tile, rl, 4 * (lane + 32 * i), uh);
        }
    }
}

// ---------------- 5: GEMM — bulk-async fills, fp16 2-pass ----------------
#define STAGE_B (3 * CHUNK_B)                 // 49152 B (Ah, Bh, Bl)
#define GEMM_SMEM (1024 + 2 * STAGE_B)        // 99328 B -> 2 CTAs/SM

#define LDSM4(r0, r1, r2, r3, addr) \
    asm volatile("ldmatrix.sync.aligned.m8n8.x4.shared.b16 {%0,%1,%2,%3}, [%4];" \
                 : "=r"(r0), "=r"(r1), "=r"(r2), "=r"(r3) : "r"(addr))

#define MMAF16(d, a, b0v, b1v) \
    asm volatile("mma.sync.aligned.m16n8k16.row.col.f32.f16.f16.f32 " \
                 "{%0,%1,%2,%3}, {%4,%5,%6,%7}, {%8,%9}, {%0,%1,%2,%3};" \
                 : "+f"(d.x), "+f"(d.y), "+f"(d.z), "+f"(d.w) \
                 : "r"(a[0]), "r"(a[1]), "r"(a[2]), "r"(a[3]), "r"(b0v), "r"(b1v))

__device__ __forceinline__ void bulk_g2s(uint32_t dst, const void* src, uint32_t bytes,
                                         uint32_t mbar) {
    asm volatile(
        "cp.async.bulk.shared::cta.global.mbarrier::complete_tx::bytes [%0], [%1], %2, [%3];"
        :: "r"(dst), "l"(src), "r"(bytes), "r"(mbar) : "memory");
}
__device__ __forceinline__ void mbar_expect(uint32_t mbar, uint32_t bytes) {
    asm volatile("mbarrier.arrive.expect_tx.shared.b64 _, [%0], %1;"
                 :: "r"(mbar), "r"(bytes) : "memory");
}
__device__ __forceinline__ void mbar_wait(uint32_t mbar, uint32_t phase) {
    uint32_t done = 0;
    while (!done)
        asm volatile("{\n\t.reg .pred p;\n\t"
                     "mbarrier.try_wait.parity.acquire.cta.shared::cta.b64 p, [%1], %2;\n\t"
                     "selp.b32 %0, 1, 0, p;\n\t}"
                     : "=r"(done) : "r"(mbar), "r"(phase) : "memory");
}

__global__ __launch_bounds__(256, 2)
void sim_gemm_tc() {
    extern __shared__ __align__(128) char smem[];
    const uint32_t sbase = (uint32_t)__cvta_generic_to_shared(smem);
    const uint32_t sb = sbase + 1024;           // buffer region

    const int tid  = threadIdx.x;
    const int lane = tid & 31;
    const int wid  = tid >> 5;
    const int wm   = wid & 1;
    const int wn   = wid >> 1;
    const int m_base = wm * 64;
    const int n_base = wn * 32;
    const int by = blockIdx.y;                   // batch tile (0..3)
    const int bx = blockIdx.x;                   // class tile (0..156)
    const int row0 = by * 128;
    const int col0 = bx * 128;

    if (tid == 0) {
        asm volatile("mbarrier.init.shared.b64 [%0], 1;" :: "r"(sbase) : "memory");
        asm volatile("mbarrier.init.shared.b64 [%0], 1;" :: "r"(sbase + 8) : "memory");
    }
    __syncthreads();

    const char* srcA  = (const char*)g_qh;
    const char* srcBh = (const char*)g_ph;
    const char* srcBl = (const char*)g_pl;

    auto fill = [&](int s, int ck) {
        const uint32_t mb = sbase + s * 8;
        const uint32_t d  = sb + s * STAGE_B;
        mbar_expect(mb, STAGE_B);
        bulk_g2s(d,               srcA  + tco(by, ck), CHUNK_B, mb);
        bulk_g2s(d + CHUNK_B,     srcBh + tco(bx, ck), CHUNK_B, mb);
        bulk_g2s(d + 2 * CHUNK_B, srcBl + tco(bx, ck), CHUNK_B, mb);
    };

    if (tid == 0) { fill(0, 0); fill(1, 1); }

    const int rA = (lane & 7) + ((lane >> 3) & 1) * 8;
    const int hA = ((lane >> 4) & 1) * 16;       // byte offset within 32B k-sub
    const int rB = (lane & 7) + ((lane >> 4) & 1) * 8;
    const int hB = ((lane >> 3) & 1) * 16;

    float4 acc[4][4];
#pragma unroll
    for (int i = 0; i < 4; i++)
#pragma unroll
        for (int j = 0; j < 4; j++) acc[i][j] = make_float4(0.f, 0.f, 0.f, 0.f);

    for (int kt = 0; kt < NCHUNK; kt++) {
        const int s = kt & 1;
        mbar_wait(sbase + s * 8, (kt >> 1) & 1);

        const uint32_t bAh = sb + s * STAGE_B;
        const uint32_t bBh = bAh + CHUNK_B;
        const uint32_t bBl = bAh + 2 * CHUNK_B;
#pragma unroll
        for (int kk = 0; kk < 4; kk++) {        // 4 x K=16 within the 64-col chunk
            uint32_t Ah[4][4], Bh[2][4], Bl[2][4];
#pragma unroll
            for (int im = 0; im < 4; im++) {
                uint32_t b = (uint32_t)((m_base + im * 16 + rA) * 128 + kk * 32 + hA);
                LDSM4(Ah[im][0], Ah[im][1], Ah[im][2], Ah[im][3], bAh + sw128(b));
            }
#pragma unroll
            for (int t2 = 0; t2 < 2; t2++) {
                uint32_t b = (uint32_t)((n_base + t2 * 16 + rB) * 128 + kk * 32 + hB);
                LDSM4(Bh[t2][0], Bh[t2][1], Bh[t2][2], Bh[t2][3], bBh + sw128(b));
                LDSM4(Bl[t2][0], Bl[t2][1], Bl[t2][2], Bl[t2][3], bBl + sw128(b));
            }
#pragma unroll
            for (int im = 0; im < 4; im++)
#pragma unroll
                for (int in = 0; in < 4; in++)
                    MMAF16(acc[im][in], Ah[im], Bh[in >> 1][(in & 1) * 2],
                           Bh[in >> 1][(in & 1) * 2 + 1]);
#pragma unroll
            for (int im = 0; im < 4; im++)
#pragma unroll
                for (int in = 0; in < 4; in++)
                    MMAF16(acc[im][in], Ah[im], Bl[in >> 1][(in & 1) * 2],
                           Bl[in >> 1][(in & 1) * 2 + 1]);
        }
        __syncthreads();                         // all warps done with stage s
        if (tid == 0 && kt + 2 < NCHUNK) fill(s, kt + 2);
    }

    // epilogue: scale by invp[col]/64, write g_sim
    const int gq = lane >> 2;
    const int qp = (lane & 3) * 2;
#pragma unroll
    for (int im = 0; im < 4; im++) {
        const int r = row0 + m_base + im * 16 + gq;
        float* row_ptr0 = g_sim + (size_t)r * C_;
        float* row_ptr1 = g_sim + (size_t)(r + 8) * C_;
#pragma unroll
        for (int in = 0; in < 4; in++) {
            const int c = col0 + n_base + in * 8 + qp;
            if (c < C_) {
                const float ip0 = g_invp[c] * BINV;
                const float ip1 = g_invp[c + 1] * BINV;
                float4 a = acc[im][in];
                float2 lo = make_float2(a.x * ip0, a.y * ip1);
                float2 hi = make_float2(a.z * ip0, a.w * ip1);
                *(float2*)(row_ptr0 + c) = lo;
                *(float2*)(row_ptr1 + c) = hi;
            }
        }
    }
    __syncthreads();
    if (tid == 0) {
        asm volatile("mbarrier.inval.shared.b64 [%0];" :: "r"(sbase) : "memory");
        asm volatile("mbarrier.inval.shared.b64 [%0];" :: "r"(sbase + 8) : "memory");
    }
}

// ---------------- 6: top-16 negatives + logsumexp per row ----------------
__global__ __launch_bounds__(256)
void topk_lse() {
    __shared__ float cand[256 * NHN];
    const int b = blockIdx.x;
    const int tid = threadIdx.x;
    const int lab = g_lab[b];
    const float* row = g_sim + (size_t)b * C_;

    float lt[NHN];
#pragma unroll
    for (int i = 0; i < NHN; i++) lt[i] = -1e30f;

    const float4* row4 = (const float4*)row;
    for (int c4 = tid; c4 < C_ / 4; c4 += 256) {
        float4 v4 = row4[c4];
        const int cb = c4 * 4;
        float vv[4] = {v4.x, v4.y, v4.z, v4.w};
#pragma unroll
        for (int j = 0; j < 4; j++) {
            if (cb + j == lab) continue;
            float v = vv[j];
            if (v > lt[NHN - 1]) {
                int k = NHN - 1;
                while (k > 0 && lt[k - 1] < v) { lt[k] = lt[k - 1]; --k; }
                lt[k] = v;
            }
        }
    }
#pragma unroll
    for (int i = 0; i < NHN; i++) cand[tid * NHN + i] = lt[i];

    for (int s = 128; s >= 1; s >>= 1) {
        __syncthreads();
        if (tid < s) {
            const float* Aa = cand + tid * NHN;
            const float* Bb = cand + (tid + s) * NHN;
            float out[NHN];
            int i = 0, j = 0;
#pragma unroll
            for (int t = 0; t < NHN; t++) {
                float a = Aa[i], bv = Bb[j];
                if (a >= bv) { out[t] = a; i++; } else { out[t] = bv; j++; }
            }
#pragma unroll
            for (int t = 0; t < NHN; t++) cand[tid * NHN + t] = out[t];
        }
    }
    __syncthreads();
    if (tid == 0) {
        float pos = row[lab];
        float mx = pos;
#pragma unroll
        for (int i = 0; i < NHN; i++) mx = fmaxf(mx, cand[i]);
        float sum = __expf(pos - mx);
#pragma unroll
        for (int i = 0; i < NHN; i++) sum += __expf(cand[i] - mx);
        g_nce[b] = mx + logf(sum) - pos;
    }
}

// ---------------- 7: alignment loss per row ----------------
__global__ __launch_bounds__(256)
void align_row(const float* __restrict__ emb, const float* __restrict__ sat,
               const float* __restrict__ neb) {
    __shared__ float red[5][8];
    const int b = blockIdx.x;
    const int tid = threadIdx.x;
    const int lab = g_lab[b];
    const float* e = emb + (size_t)b * DE;
    const float* s = sat + (size_t)b * DE;
    const float* p = neb + (size_t)lab * DE;
    float ee = 0, ss = 0, pp = 0, ep = 0, sp = 0;
    for (int i = tid; i < DE; i += 256) {
        float ev = e[i], sv = s[i], pv = p[i];
        ee += ev * ev; ss += sv * sv; pp += pv * pv;
        ep += ev * pv; sp += sv * pv;
    }
#pragma unroll
    for (int o = 16; o; o >>= 1) {
        ee += __shfl_xor_sync(0xffffffffu, ee, o);
        ss += __shfl_xor_sync(0xffffffffu, ss, o);
        pp += __shfl_xor_sync(0xffffffffu, pp, o);
        ep += __shfl_xor_sync(0xffffffffu, ep, o);
        sp += __shfl_xor_sync(0xffffffffu, sp, o);
    }
    int w = tid >> 5;
    if ((tid & 31) == 0) {
        red[0][w] = ee; red[1][w] = ss; red[2][w] = pp; red[3][w] = ep; red[4][w] = sp;
    }
    __syncthreads();
    if (tid == 0) {
        float a0 = 0, a1 = 0, a2 = 0, a3 = 0, a4 = 0;
        for (int i = 0; i < 8; i++) {
            a0 += red[0][i]; a1 += red[1][i]; a2 += red[2][i];
            a3 += red[3][i]; a4 += red[4][i];
        }
        float dn = fmaxf(sqrtf(a0), 1e-12f);
        float sn = fmaxf(sqrtf(a1), 1e-12f);
        float pn = fmaxf(sqrtf(a2), 1e-12f);
        g_align[b] = 0.5f * ((1.0f - a3 / (dn * pn)) + (1.0f - a4 / (sn * pn)));
    }
}

// ---------------- 8: final scalar reduction ----------------
__global__ __launch_bounds__(512)
void finalize(float* __restrict__ out_loss) {
    __shared__ float s1[512], s2[512];
    int t = threadIdx.x;
    s1[t] = g_nce[t];
    s2[t] = g_align[t];
    __syncthreads();
    for (int s = 256; s >= 1; s >>= 1) {
        if (t < s) { s1[t] += s1[t + s]; s2[t] += s2[t + s]; }
        __syncthreads();
    }
    if (t == 0) {
        out_loss[0] = s1[0] / (float)B_;
        out_loss[1] = s2[0] / (float)B_;
    }
}

// ---------------- launch ----------------
extern "C" void kernel_launch(void* const* d_in, const int* in_sizes, int n_in,
                              void* d_out, int out_size) {
    const float* pf    = (const float*)d_in[0];     // [512, 8, 256]
    const float* emb   = (const float*)d_in[1];     // [512, 512]
    const float* sat   = (const float*)d_in[2];     // [512, 512]
    const float* pbank = (const float*)d_in[3];     // [20000, 8, 256]
    const float* ebank = (const float*)d_in[4];     // [20000, 512]
    const int*   labs  = (const int*)d_in[5];       // [512] int32/int64 auto-detected

    const int P = in_sizes[3];   // 40,960,000
    const int E = in_sizes[4];   // 10,240,000

    float* out    = (float*)d_out;
    float* out_pb = out;
    float* out_eb = out + P;
    float* out_ls = out + P + E;

    static bool attr_done = false;
    if (!attr_done) {
        cudaFuncSetAttribute(sim_gemm_tc,
                             cudaFuncAttributeMaxDynamicSharedMemorySize, GEMM_SMEM);
        attr_done = true;
    }

    // 0. labels + inverse map
    clear_invmap<<<(C_ + 255) / 256, 256>>>();
    decode_labels<<<1, B_>>>(labs);
    // 1. part-bank copy + EMA fused (one pass)
    copy_part_ema<<<2048, 256>>>((const float4*)pbank, (const float4*)pf,
                                 (float4*)out_pb, P / 4);
    // 2. fused embed copy + EMA + norms + fp16 splits (tiled layout) + q prep
    proto_fused<<<(C_ + B_ + 7) / 8, 256>>>(ebank, emb, out_eb);
    // 3. GEMM (bulk-async fills, fp16 2-pass, 2 CTA/SM)
    dim3 ggrid(NTILE_C, B_ / 128);
    sim_gemm_tc<<<ggrid, 256, GEMM_SMEM>>>();
    // 4. top-k + logsumexp
    topk_lse<<<B_, 256>>>();
    // 5. alignment
    align_row<<<B_, 256>>>(emb, sat, out_eb);
    // 6. finalize scalars
    finalize<<<1, 512>>>(out_ls);
}